// round 14
// baseline (speedup 1.0000x reference)
#include <cuda_runtime.h>
#include <cuda_fp16.h>
#include <cstdint>

// Lingunet5Filter — HMMA fp16 GEMM (CTA 128x128, 2 CTAs/SM) with K-chunked
// double-buffered B pipeline + fp16-intermediate instance norm (merged launch).
//   GEMM: D = fp16(F)*fp16(X), fp32 accum; levels 0-3 write fp16 Y scratch +
//   per-(b,o,tile) partial stats. Norm: grid (4096,4), reduce partials ->
//   mean/rstd, read fp16 Y, write fp32. Level 4: direct fp32.

#define EPSN   1e-5f
#define PITCH  136   // A: fp16 elems per smem row (272 B), ldmatrix conflict-free
#define PITCHB 40    // B chunk: fp16 elems per row (80 B), ldmatrix conflict-free
#define FPITCH 132   // float elems per epilogue bounce row

// scratch: fp16 Y for levels 0-3, partial stats
__device__ __half g_yh[89128960];
__device__ float  g_p1[696320];
__device__ float  g_p2[696320];

static __device__ __forceinline__ uint32_t smem_u32(const void* p) {
    uint32_t a;
    asm("{ .reg .u64 t; cvta.to.shared.u64 t, %1; cvt.u32.u64 %0, t; }" : "=r"(a) : "l"(p));
    return a;
}
static __device__ __forceinline__ uint32_t pack_h2(float a, float b) {
    __half2 t = __floats2half2_rn(a, b);
    return *reinterpret_cast<uint32_t*>(&t);
}

#define LDSM4(r, addr)                                                          \
    asm volatile("ldmatrix.sync.aligned.m8n8.x4.shared.b16 {%0,%1,%2,%3}, [%4];" \
                 : "=r"((r)[0]), "=r"((r)[1]), "=r"((r)[2]), "=r"((r)[3])        \
                 : "r"(addr))

#define MMA16816(d, a, b0, b1)                                                  \
    asm volatile("mma.sync.aligned.m16n8k16.row.col.f32.f16.f16.f32 "            \
                 "{%0,%1,%2,%3}, {%4,%5,%6,%7}, {%8,%9}, {%0,%1,%2,%3};"         \
                 : "+f"((d)[0]), "+f"((d)[1]), "+f"((d)[2]), "+f"((d)[3])        \
                 : "r"((a)[0]), "r"((a)[1]), "r"((a)[2]), "r"((a)[3]),           \
                   "r"(b0), "r"(b1))

// ---------------- kernel 1: pipelined HMMA GEMM ----------------
__global__ __launch_bounds__(256, 2)
void lg5_hmma(const float* __restrict__ x0, const float* __restrict__ x1,
              const float* __restrict__ x2, const float* __restrict__ x3,
              const float* __restrict__ x4,
              const float* __restrict__ f0, const float* __restrict__ f1,
              const float* __restrict__ f2, const float* __restrict__ f3,
              const float* __restrict__ f4,
              float* __restrict__ out) {
    extern __shared__ char smem[];
    __half* AH  = (__half*)smem;                       // 128 x PITCH  (34816 B)
    __half* BH0 = (__half*)(smem + 34816);             // 128 x PITCHB (10240 B)
    __half* BH1 = (__half*)(smem + 45056);             // 128 x PITCHB
    float*  T   = (float*)smem;                        // epilogue overlay

    __shared__ float sp1[2][128], sp2[2][128];

    // ---- level / tile decode (n-tiles of 128) ----
    const int bx = blockIdx.x;
    int L, t0;
    if (bx < 4096)      { L = 0; t0 = bx; }
    else if (bx < 5120) { L = 1; t0 = bx - 4096; }
    else if (bx < 5376) { L = 2; t0 = bx - 5120; }
    else if (bx < 5440) { L = 3; t0 = bx - 5376; }
    else                { L = 4; t0 = bx - 5440; }

    int N, nT;
    long long yoff;
    const float *X, *F;
    if (L == 0)      { N = 16384; nT = 128; yoff = 0LL;        X = x0; F = f0; }
    else if (L == 1) { N = 4096;  nT = 32;  yoff = 67108864LL; X = x1; F = f1; }
    else if (L == 2) { N = 1024;  nT = 8;   yoff = 83886080LL; X = x2; F = f2; }
    else if (L == 3) { N = 256;   nT = 2;   yoff = 88080384LL; X = x3; F = f3; }
    else             { N = 64;    nT = 1;   yoff = 89128960LL; X = x4; F = f4; }

    const int b    = t0 / nT;
    const int tile = t0 - b * nT;
    const int n0   = tile * 128;

    X += (size_t)b * 128 * N;
    F += (size_t)b * 128 * 128;

    const int tid = threadIdx.x;

    // ---- B chunk load mapping: n = tid&127, k-quarter cq = tid>>7 ----
    const int n_b = tid & 127;
    const int cq  = tid >> 7;
    const bool nv = (n0 + n_b) < N;        // level-4 tail rows
    const float* xb = X + (size_t)n0 + n_b;
    __half* bst = (cq ? BH0 + 16 : BH0) + n_b * PITCHB;  // chunk store base (buf 0)

    float rb[16];
    // ---- prologue: issue chunk-0 LDGs ----
    {
        const int kbase = cq * 16;
#pragma unroll
        for (int i = 0; i < 16; i++)
            rb[i] = nv ? xb[(size_t)(kbase + i) * N] : 0.f;
    }

    // ---- load F -> AH (overlaps with chunk-0 LDGs in flight) ----
#pragma unroll
    for (int i = 0; i < 16; i++) {
        const int e   = (i * 256 + tid) * 4;
        const int row = e >> 7;
        const int k   = e & 127;
        const float4 f = *(const float4*)(F + e);
        uint2 hi2;
        hi2.x = pack_h2(f.x, f.y);
        hi2.y = pack_h2(f.z, f.w);
        *(uint2*)(AH + row * PITCH + k) = hi2;
    }

    // ---- store chunk 0 ----
#pragma unroll
    for (int i = 0; i < 16; i += 2)
        *(uint32_t*)(bst + i) = pack_h2(rb[i], rb[i + 1]);
    __syncthreads();

    // ---- mainloop: 4 K-chunks of 32, double-buffered ----
    const int wid  = tid >> 5;
    const int lane = tid & 31;
    const int wm   = (wid >> 1) * 32;
    const int wn   = (wid & 1) * 64;

    float d[16][4];
#pragma unroll
    for (int i = 0; i < 16; i++)
#pragma unroll
        for (int j = 0; j < 4; j++) d[i][j] = 0.f;

    const int arow = lane & 15;
    const int acol = (lane >> 4) * 8;
    const int brow = (lane & 7) + ((lane >> 4) << 3);
    const int bcol = ((lane >> 3) & 1) * 8;

    const uint32_t aB0 = smem_u32(AH + (wm + arow) * PITCH + acol);
    const uint32_t aB1 = aB0 + 16 * PITCH * 2;
    const uint32_t bF0 = smem_u32(BH0 + (wn + brow) * PITCHB + bcol);
    const uint32_t bF1 = smem_u32(BH1 + (wn + brow) * PITCHB + bcol);
    const uint32_t bufStride = 10240;   // BH1 - BH0 in bytes (store side)

#pragma unroll
    for (int chunk = 0; chunk < 4; chunk++) {
        // prefetch next chunk's LDGs
        if (chunk < 3) {
            const int kbase = (chunk + 1) * 32 + cq * 16;
#pragma unroll
            for (int i = 0; i < 16; i++)
                rb[i] = nv ? xb[(size_t)(kbase + i) * N] : 0.f;
        }

        // MMA on current chunk (2 k-steps of 16)
        const uint32_t bBuf = (chunk & 1) ? bF1 : bF0;
#pragma unroll
        for (int ks = 0; ks < 2; ks++) {
            const uint32_t koA = (chunk * 2 + ks) * 32;
            const uint32_t koB = ks * 32;
            uint32_t bb[4][4];
#pragma unroll
            for (int t = 0; t < 4; t++)
                LDSM4(bb[t], bBuf + t * (16 * PITCHB * 2) + koB);

            uint32_t a0[4], a1[4];
            LDSM4(a0, aB0 + koA);
            LDSM4(a1, aB1 + koA);
#pragma unroll
            for (int t = 0; t < 4; t++) {
                MMA16816(d[2 * t + 0], a0, bb[t][0], bb[t][1]);
                MMA16816(d[2 * t + 1], a0, bb[t][2], bb[t][3]);
                MMA16816(d[2 * t + 8], a1, bb[t][0], bb[t][1]);
                MMA16816(d[2 * t + 9], a1, bb[t][2], bb[t][3]);
            }
        }

        // store next chunk into the other buffer and sync
        if (chunk < 3) {
            __half* dst = (__half*)((char*)bst + (((chunk + 1) & 1) ? bufStride : 0));
#pragma unroll
            for (int i = 0; i < 16; i += 2)
                *(uint32_t*)(dst + i) = pack_h2(rb[i], rb[i + 1]);
            __syncthreads();
        }
    }

    // ---- partial stats from registers (levels 0-3), write-only ----
    if (L < 4) {
        float s1[4] = {0.f, 0.f, 0.f, 0.f}, s2[4] = {0.f, 0.f, 0.f, 0.f};
#pragma unroll
        for (int mi = 0; mi < 2; mi++)
#pragma unroll
            for (int nj = 0; nj < 8; nj++) {
                const float* dd = d[mi * 8 + nj];
                s1[mi * 2 + 0] += dd[0] + dd[1];
                s2[mi * 2 + 0] += dd[0] * dd[0] + dd[1] * dd[1];
                s1[mi * 2 + 1] += dd[2] + dd[3];
                s2[mi * 2 + 1] += dd[2] * dd[2] + dd[3] * dd[3];
            }
#pragma unroll
        for (int dlt = 1; dlt <= 2; dlt <<= 1)
#pragma unroll
            for (int i = 0; i < 4; i++) {
                s1[i] += __shfl_xor_sync(0xffffffffu, s1[i], dlt);
                s2[i] += __shfl_xor_sync(0xffffffffu, s2[i], dlt);
            }
        if ((lane & 3) == 0) {
#pragma unroll
            for (int i = 0; i < 4; i++) {
                const int row = wm + (i >> 1) * 16 + (i & 1) * 8 + (lane >> 2);
                sp1[wid & 1][row] = s1[i];
                sp2[wid & 1][row] = s2[i];
            }
        }
        __syncthreads();
        const long long poff = (L == 0) ? 0LL : (L == 1) ? 524288LL
                              : (L == 2) ? 655360LL : 688128LL;
        const size_t pidx = (size_t)poff + ((size_t)b * nT + tile) * 128 + tid;
        if (tid < 128) {
            g_p1[pidx] = sp1[0][tid] + sp1[1][tid];
            g_p2[pidx] = sp2[0][tid] + sp2[1][tid];
        }
    }
    __syncthreads();   // all warps done with AH/BH (and sp) before T overlay

    // ---- epilogue: d frags -> smem bounce -> coalesced store ----
#pragma unroll
    for (int mi = 0; mi < 2; mi++)
#pragma unroll
        for (int nj = 0; nj < 8; nj++) {
            const int row = wm + mi * 16 + (lane >> 2);
            const int col = wn + nj * 8 + 2 * (lane & 3);
            const float* dd = d[mi * 8 + nj];
            *(float2*)&T[row * FPITCH + col]       = make_float2(dd[0], dd[1]);
            *(float2*)&T[(row + 8) * FPITCH + col] = make_float2(dd[2], dd[3]);
        }
    __syncthreads();

    const int r0 = tid >> 5;
    const int c0 = (tid & 31) * 4;
    if (L < 4) {
        __half* Yh = g_yh + yoff + (size_t)b * 128 * N;
#pragma unroll
        for (int i = 0; i < 16; i++) {
            const int row = r0 + i * 8;
            const float4 v = *(const float4*)&T[row * FPITCH + c0];
            uint2 h;
            h.x = pack_h2(v.x, v.y);
            h.y = pack_h2(v.z, v.w);
            *(uint2*)&Yh[(size_t)row * N + n0 + c0] = h;
        }
    } else {
        float* Y = out + yoff + (size_t)b * 128 * N;
        const bool sv = (c0 < 64);   // N = 64, n0 = 0
#pragma unroll
        for (int i = 0; i < 16; i++) {
            const int row = r0 + i * 8;
            const float4 v = *(const float4*)&T[row * FPITCH + c0];
            if (sv) *(float4*)&Y[(size_t)row * N + c0] = v;
        }
    }
}

// ---------------- kernel 2: merged norm, grid (4096, 4) ----------------
template <int ITERS>
static __device__ __forceinline__
void norm_row(float* __restrict__ out, size_t yoff, int N, size_t poff, int nT, int bo) {
    const int b   = bo >> 7;
    const int o   = bo & 127;
    const int tid = threadIdx.x;

    const size_t pbase = poff + ((size_t)b * nT) * 128 + o;
    float s1 = 0.f, s2 = 0.f;
    for (int t = tid; t < nT; t += 256) {
        s1 += g_p1[pbase + (size_t)t * 128];
        s2 += g_p2[pbase + (size_t)t * 128];
    }
#pragma unroll
    for (int dl = 16; dl >= 1; dl >>= 1) {
        s1 += __shfl_xor_sync(0xffffffffu, s1, dl);
        s2 += __shfl_xor_sync(0xffffffffu, s2, dl);
    }
    __shared__ float a1[8], a2[8], st[2];
    const int w = tid >> 5, lane = tid & 31;
    if (lane == 0) { a1[w] = s1; a2[w] = s2; }
    __syncthreads();
    if (tid == 0) {
        float S1 = 0.f, S2 = 0.f;
#pragma unroll
        for (int i = 0; i < 8; i++) { S1 += a1[i]; S2 += a2[i]; }
        const float invN = 1.0f / (float)N;
        const float mean = S1 * invN;
        const float var  = S2 * invN - mean * mean;
        st[0] = mean;
        st[1] = rsqrtf(var + EPSN);
    }
    __syncthreads();
    const float mean = st[0], rstd = st[1];

    const __half* rh = g_yh + yoff + (size_t)bo * N;
    float*        rf = out  + yoff + (size_t)bo * N;
#pragma unroll
    for (int i = 0; i < ITERS; i++) {
        const int idx = (i * 256 + tid) * 8;
        if (idx < N) {
            const uint4 hv = *(const uint4*)(rh + idx);
            const uint32_t hw[4] = {hv.x, hv.y, hv.z, hv.w};
            float4 o0, o1;
            float* op[8] = {&o0.x, &o0.y, &o0.z, &o0.w, &o1.x, &o1.y, &o1.z, &o1.w};
#pragma unroll
            for (int j = 0; j < 4; j++) {
                const __half2 h2 = *reinterpret_cast<const __half2*>(&hw[j]);
                const float2 f2 = __half22float2(h2);
                *op[2 * j]     = (f2.x - mean) * rstd;
                *op[2 * j + 1] = (f2.y - mean) * rstd;
            }
            *(float4*)(rf + idx)     = o0;
            *(float4*)(rf + idx + 4) = o1;
        }
    }
}

__global__ __launch_bounds__(256)
void lg5_norm_all(float* __restrict__ out) {
    const int bo = blockIdx.x;
    if (blockIdx.y == 0)      norm_row<8>(out, 0,           16384, 0,      128, bo);
    else if (blockIdx.y == 1) norm_row<2>(out, 67108864ULL, 4096,  524288, 32,  bo);
    else if (blockIdx.y == 2) norm_row<1>(out, 83886080ULL, 1024,  655360, 8,   bo);
    else                      norm_row<1>(out, 88080384ULL, 256,   688128, 2,   bo);
}

// ---------------- launch ----------------
extern "C" void kernel_launch(void* const* d_in, const int* in_sizes, int n_in,
                              void* d_out, int out_size) {
    const float* xs[5] = {0, 0, 0, 0, 0};
    const float* fs[5] = {0, 0, 0, 0, 0};
    int fc = 0;
    for (int i = 0; i < n_in; i++) {
        const float* p = (const float*)d_in[i];
        switch (in_sizes[i]) {
            case 67108864: xs[0] = p; break;
            case 16777216: xs[1] = p; break;
            case 4194304:  xs[2] = p; break;
            case 1048576:  xs[3] = p; break;
            case 262144:   xs[4] = p; break;
            case 524288:   if (fc < 5) fs[fc++] = p; break;
        }
    }
    float* out = (float*)d_out;

    const int smem_bytes = 69632;   // max(AH+2*Bbuf = 55296, epilogue T = 67584) + pad
    cudaFuncSetAttribute(lg5_hmma, cudaFuncAttributeMaxDynamicSharedMemorySize, smem_bytes);
    lg5_hmma<<<5472, 256, smem_bytes>>>(xs[0], xs[1], xs[2], xs[3], xs[4],
                                        fs[0], fs[1], fs[2], fs[3], fs[4], out);

    lg5_norm_all<<<dim3(4096, 4), 256>>>(out);
}

// round 15
// speedup vs baseline: 1.0444x; 1.0444x over previous
#include <cuda_runtime.h>
#include <cuda_fp16.h>
#include <cstdint>

// Lingunet5Filter — HMMA fp16 GEMM (CTA 128x128, 2 CTAs/SM), B kept K-major in
// smem + ldmatrix.trans (streaming float4 global loads, no strided columns).
//   GEMM: D = fp16(F)*fp16(X), fp32 accum; levels 0-3 write fp16 Y scratch +
//   per-(b,o,tile) partial stats. Norm: grid (4096,4), reduce partials ->
//   mean/rstd, read fp16 Y, write fp32. Level 4: direct fp32.

#define EPSN   1e-5f
#define PITCH  136   // A: fp16 elems per smem row (272 B), ldmatrix conflict-free
#define PITCHB 136   // B: fp16 elems per k-row (272 B), ldmatrix conflict-free
#define FPITCH 132   // float elems per epilogue bounce row

// scratch: fp16 Y for levels 0-3, partial stats
__device__ __half g_yh[89128960];
__device__ float  g_p1[696320];
__device__ float  g_p2[696320];

static __device__ __forceinline__ uint32_t smem_u32(const void* p) {
    uint32_t a;
    asm("{ .reg .u64 t; cvta.to.shared.u64 t, %1; cvt.u32.u64 %0, t; }" : "=r"(a) : "l"(p));
    return a;
}
static __device__ __forceinline__ uint32_t pack_h2(float a, float b) {
    __half2 t = __floats2half2_rn(a, b);
    return *reinterpret_cast<uint32_t*>(&t);
}

#define LDSM4(r, addr)                                                          \
    asm volatile("ldmatrix.sync.aligned.m8n8.x4.shared.b16 {%0,%1,%2,%3}, [%4];" \
                 : "=r"((r)[0]), "=r"((r)[1]), "=r"((r)[2]), "=r"((r)[3])        \
                 : "r"(addr))

#define LDSM4T(r, addr)                                                              \
    asm volatile("ldmatrix.sync.aligned.m8n8.x4.trans.shared.b16 {%0,%1,%2,%3}, [%4];" \
                 : "=r"((r)[0]), "=r"((r)[1]), "=r"((r)[2]), "=r"((r)[3])            \
                 : "r"(addr))

#define MMA16816(d, a, b0, b1)                                                  \
    asm volatile("mma.sync.aligned.m16n8k16.row.col.f32.f16.f16.f32 "            \
                 "{%0,%1,%2,%3}, {%4,%5,%6,%7}, {%8,%9}, {%0,%1,%2,%3};"         \
                 : "+f"((d)[0]), "+f"((d)[1]), "+f"((d)[2]), "+f"((d)[3])        \
                 : "r"((a)[0]), "r"((a)[1]), "r"((a)[2]), "r"((a)[3]),           \
                   "r"(b0), "r"(b1))

// ---------------- kernel 1: HMMA GEMM ----------------
__global__ __launch_bounds__(256, 2)
void lg5_hmma(const float* __restrict__ x0, const float* __restrict__ x1,
              const float* __restrict__ x2, const float* __restrict__ x3,
              const float* __restrict__ x4,
              const float* __restrict__ f0, const float* __restrict__ f1,
              const float* __restrict__ f2, const float* __restrict__ f3,
              const float* __restrict__ f4,
              float* __restrict__ out) {
    extern __shared__ char smem[];
    __half* AH = (__half*)smem;             // 128 x PITCH  (m-major, k contiguous)
    __half* BH = AH + 128 * PITCH;          // 128 x PITCHB (k-major, n contiguous)
    float*  T  = (float*)smem;              // epilogue overlay (128 x FPITCH)

    __shared__ float sp1[2][128], sp2[2][128];

    // ---- level / tile decode (n-tiles of 128) ----
    const int bx = blockIdx.x;
    int L, t0;
    if (bx < 4096)      { L = 0; t0 = bx; }
    else if (bx < 5120) { L = 1; t0 = bx - 4096; }
    else if (bx < 5376) { L = 2; t0 = bx - 5120; }
    else if (bx < 5440) { L = 3; t0 = bx - 5376; }
    else                { L = 4; t0 = bx - 5440; }

    int N, nT;
    long long yoff;
    const float *X, *F;
    if (L == 0)      { N = 16384; nT = 128; yoff = 0LL;        X = x0; F = f0; }
    else if (L == 1) { N = 4096;  nT = 32;  yoff = 67108864LL; X = x1; F = f1; }
    else if (L == 2) { N = 1024;  nT = 8;   yoff = 83886080LL; X = x2; F = f2; }
    else if (L == 3) { N = 256;   nT = 2;   yoff = 88080384LL; X = x3; F = f3; }
    else             { N = 64;    nT = 1;   yoff = 89128960LL; X = x4; F = f4; }

    const int b    = t0 / nT;
    const int tile = t0 - b * nT;
    const int n0   = tile * 128;

    X += (size_t)b * 128 * N;
    F += (size_t)b * 128 * 128;

    const int tid = threadIdx.x;

    // ---- load X tile -> BH, K-major, streaming float4 rows ----
    // thread i of iter: k = lin>>5, n = (lin&31)*4; fully coalesced LDG.128.
    {
        const int nvmax = N - n0;   // 128 normally; 64 for the L4 tail
#pragma unroll
        for (int i = 0; i < 16; i++) {
            const int lin = i * 256 + tid;
            const int k   = lin >> 5;
            const int n   = (lin & 31) * 4;
            float4 v = make_float4(0.f, 0.f, 0.f, 0.f);
            if (n < nvmax) v = *(const float4*)(X + (size_t)k * N + n0 + n);
            uint2 h;
            h.x = pack_h2(v.x, v.y);
            h.y = pack_h2(v.z, v.w);
            *(uint2*)(BH + k * PITCHB + n) = h;
        }
    }

    // ---- load F -> AH (m-major) ----
#pragma unroll
    for (int i = 0; i < 16; i++) {
        const int e   = (i * 256 + tid) * 4;
        const int row = e >> 7;
        const int k   = e & 127;
        const float4 f = *(const float4*)(F + e);
        uint2 hi2;
        hi2.x = pack_h2(f.x, f.y);
        hi2.y = pack_h2(f.z, f.w);
        *(uint2*)(AH + row * PITCH + k) = hi2;
    }
    __syncthreads();

    // ---- HMMA mainloop: warp tile 32m x 64n, 8 k-steps ----
    const int wid  = tid >> 5;
    const int lane = tid & 31;
    const int wm   = (wid >> 1) * 32;
    const int wn   = (wid & 1) * 64;

    float d[16][4];
#pragma unroll
    for (int i = 0; i < 16; i++)
#pragma unroll
        for (int j = 0; j < 4; j++) d[i][j] = 0.f;

    const int arow = lane & 15;
    const int acol = (lane >> 4) * 8;
    // B (trans): lane -> k = lane&15 within k16, n = (lane>>4)*8 within n16
    const int bkl = lane & 15;
    const int bnl = (lane >> 4) * 8;

    const uint32_t aB0 = smem_u32(AH + (wm + arow) * PITCH + acol);
    const uint32_t aB1 = aB0 + 16 * PITCH * 2;
    const uint32_t bB  = smem_u32(BH + bkl * PITCHB + wn + bnl);

#pragma unroll
    for (int ks = 0; ks < 8; ks++) {
        const uint32_t koA = ks * 32;                 // A: 16 halves along k
        const uint32_t koB = ks * 16 * PITCHB * 2;    // B: 16 k-rows
        uint32_t bb[4][4];
#pragma unroll
        for (int t = 0; t < 4; t++)
            LDSM4T(bb[t], bB + koB + t * 32);         // t: 16 n per tile (32 B)

        uint32_t a0[4], a1[4];
        LDSM4(a0, aB0 + koA);
        LDSM4(a1, aB1 + koA);
#pragma unroll
        for (int t = 0; t < 4; t++) {
            MMA16816(d[2 * t + 0], a0, bb[t][0], bb[t][1]);
            MMA16816(d[2 * t + 1], a0, bb[t][2], bb[t][3]);
            MMA16816(d[2 * t + 8], a1, bb[t][0], bb[t][1]);
            MMA16816(d[2 * t + 9], a1, bb[t][2], bb[t][3]);
        }
    }

    // ---- partial stats from registers (levels 0-3), write-only ----
    if (L < 4) {
        float s1[4] = {0.f, 0.f, 0.f, 0.f}, s2[4] = {0.f, 0.f, 0.f, 0.f};
#pragma unroll
        for (int mi = 0; mi < 2; mi++)
#pragma unroll
            for (int nj = 0; nj < 8; nj++) {
                const float* dd = d[mi * 8 + nj];
                s1[mi * 2 + 0] += dd[0] + dd[1];
                s2[mi * 2 + 0] += dd[0] * dd[0] + dd[1] * dd[1];
                s1[mi * 2 + 1] += dd[2] + dd[3];
                s2[mi * 2 + 1] += dd[2] * dd[2] + dd[3] * dd[3];
            }
#pragma unroll
        for (int dlt = 1; dlt <= 2; dlt <<= 1)
#pragma unroll
            for (int i = 0; i < 4; i++) {
                s1[i] += __shfl_xor_sync(0xffffffffu, s1[i], dlt);
                s2[i] += __shfl_xor_sync(0xffffffffu, s2[i], dlt);
            }
        if ((lane & 3) == 0) {
#pragma unroll
            for (int i = 0; i < 4; i++) {
                const int row = wm + (i >> 1) * 16 + (i & 1) * 8 + (lane >> 2);
                sp1[wid & 1][row] = s1[i];
                sp2[wid & 1][row] = s2[i];
            }
        }
        __syncthreads();
        const long long poff = (L == 0) ? 0LL : (L == 1) ? 524288LL
                              : (L == 2) ? 655360LL : 688128LL;
        const size_t pidx = (size_t)poff + ((size_t)b * nT + tile) * 128 + tid;
        if (tid < 128) {
            g_p1[pidx] = sp1[0][tid] + sp1[1][tid];
            g_p2[pidx] = sp2[0][tid] + sp2[1][tid];
        }
    }
    __syncthreads();   // all warps done with AH/BH (and sp) before T overlay

    // ---- epilogue: d frags -> smem bounce -> coalesced store ----
#pragma unroll
    for (int mi = 0; mi < 2; mi++)
#pragma unroll
        for (int nj = 0; nj < 8; nj++) {
            const int row = wm + mi * 16 + (lane >> 2);
            const int col = wn + nj * 8 + 2 * (lane & 3);
            const float* dd = d[mi * 8 + nj];
            *(float2*)&T[row * FPITCH + col]       = make_float2(dd[0], dd[1]);
            *(float2*)&T[(row + 8) * FPITCH + col] = make_float2(dd[2], dd[3]);
        }
    __syncthreads();

    const int r0 = tid >> 5;
    const int c0 = (tid & 31) * 4;
    if (L < 4) {
        __half* Yh = g_yh + yoff + (size_t)b * 128 * N;
#pragma unroll
        for (int i = 0; i < 16; i++) {
            const int row = r0 + i * 8;
            const float4 v = *(const float4*)&T[row * FPITCH + c0];
            uint2 h;
            h.x = pack_h2(v.x, v.y);
            h.y = pack_h2(v.z, v.w);
            *(uint2*)&Yh[(size_t)row * N + n0 + c0] = h;
        }
    } else {
        float* Y = out + yoff + (size_t)b * 128 * N;
        const bool sv = (c0 < 64);   // N = 64, n0 = 0
#pragma unroll
        for (int i = 0; i < 16; i++) {
            const int row = r0 + i * 8;
            const float4 v = *(const float4*)&T[row * FPITCH + c0];
            if (sv) *(float4*)&Y[(size_t)row * N + c0] = v;
        }
    }
}

// ---------------- kernel 2: merged norm, grid (4096, 4) ----------------
template <int ITERS>
static __device__ __forceinline__
void norm_row(float* __restrict__ out, size_t yoff, int N, size_t poff, int nT, int bo) {
    const int b   = bo >> 7;
    const int o   = bo & 127;
    const int tid = threadIdx.x;

    const size_t pbase = poff + ((size_t)b * nT) * 128 + o;
    float s1 = 0.f, s2 = 0.f;
    for (int t = tid; t < nT; t += 256) {
        s1 += g_p1[pbase + (size_t)t * 128];
        s2 += g_p2[pbase + (size_t)t * 128];
    }
#pragma unroll
    for (int dl = 16; dl >= 1; dl >>= 1) {
        s1 += __shfl_xor_sync(0xffffffffu, s1, dl);
        s2 += __shfl_xor_sync(0xffffffffu, s2, dl);
    }
    __shared__ float a1[8], a2[8], st[2];
    const int w = tid >> 5, lane = tid & 31;
    if (lane == 0) { a1[w] = s1; a2[w] = s2; }
    __syncthreads();
    if (tid == 0) {
        float S1 = 0.f, S2 = 0.f;
#pragma unroll
        for (int i = 0; i < 8; i++) { S1 += a1[i]; S2 += a2[i]; }
        const float invN = 1.0f / (float)N;
        const float mean = S1 * invN;
        const float var  = S2 * invN - mean * mean;
        st[0] = mean;
        st[1] = rsqrtf(var + EPSN);
    }
    __syncthreads();
    const float mean = st[0], rstd = st[1];

    const __half* rh = g_yh + yoff + (size_t)bo * N;
    float*        rf = out  + yoff + (size_t)bo * N;
#pragma unroll
    for (int i = 0; i < ITERS; i++) {
        const int idx = (i * 256 + tid) * 8;
        if (idx < N) {
            const uint4 hv = *(const uint4*)(rh + idx);
            const uint32_t hw[4] = {hv.x, hv.y, hv.z, hv.w};
            float4 o0, o1;
            float* op[8] = {&o0.x, &o0.y, &o0.z, &o0.w, &o1.x, &o1.y, &o1.z, &o1.w};
#pragma unroll
            for (int j = 0; j < 4; j++) {
                const __half2 h2 = *reinterpret_cast<const __half2*>(&hw[j]);
                const float2 f2 = __half22float2(h2);
                *op[2 * j]     = (f2.x - mean) * rstd;
                *op[2 * j + 1] = (f2.y - mean) * rstd;
            }
            *(float4*)(rf + idx)     = o0;
            *(float4*)(rf + idx + 4) = o1;
        }
    }
}

__global__ __launch_bounds__(256)
void lg5_norm_all(float* __restrict__ out) {
    const int bo = blockIdx.x;
    if (blockIdx.y == 0)      norm_row<8>(out, 0,           16384, 0,      128, bo);
    else if (blockIdx.y == 1) norm_row<2>(out, 67108864ULL, 4096,  524288, 32,  bo);
    else if (blockIdx.y == 2) norm_row<1>(out, 83886080ULL, 1024,  655360, 8,   bo);
    else                      norm_row<1>(out, 88080384ULL, 256,   688128, 2,   bo);
}

// ---------------- launch ----------------
extern "C" void kernel_launch(void* const* d_in, const int* in_sizes, int n_in,
                              void* d_out, int out_size) {
    const float* xs[5] = {0, 0, 0, 0, 0};
    const float* fs[5] = {0, 0, 0, 0, 0};
    int fc = 0;
    for (int i = 0; i < n_in; i++) {
        const float* p = (const float*)d_in[i];
        switch (in_sizes[i]) {
            case 67108864: xs[0] = p; break;
            case 16777216: xs[1] = p; break;
            case 4194304:  xs[2] = p; break;
            case 1048576:  xs[3] = p; break;
            case 262144:   xs[4] = p; break;
            case 524288:   if (fc < 5) fs[fc++] = p; break;
        }
    }
    float* out = (float*)d_out;

    const int smem_bytes = 2 * 128 * PITCH * 2;   // AH + BH = 69632 B
    cudaFuncSetAttribute(lg5_hmma, cudaFuncAttributeMaxDynamicSharedMemorySize, smem_bytes);
    lg5_hmma<<<5472, 256, smem_bytes>>>(xs[0], xs[1], xs[2], xs[3], xs[4],
                                        fs[0], fs[1], fs[2], fs[3], fs[4], out);

    lg5_norm_all<<<dim3(4096, 4), 256>>>(out);
}

// round 16
// speedup vs baseline: 1.0610x; 1.0159x over previous
#include <cuda_runtime.h>
#include <cuda_fp16.h>
#include <cstdint>

// Lingunet5Filter — HMMA fp16 GEMM (CTA 128x128, 2 CTAs/SM), K-major B via
// ldmatrix.trans, 4x K-chunk double-buffered pipeline (streaming LDG.128
// prefetch overlapped with MMA). Levels 0-3: fp16 Y scratch + partial stats;
// merged norm launch reads fp16, writes fp32. Level 4: direct fp32.

#define EPSN   1e-5f
#define PITCH  136   // A: fp16 elems per smem row (272 B), ldmatrix conflict-free
#define PITCHB 136   // B: fp16 elems per k-row (272 B), ldmatrix.trans conflict-free
#define FPITCH 132   // float elems per epilogue bounce row

// scratch: fp16 Y for levels 0-3, partial stats
__device__ __half g_yh[89128960];
__device__ float  g_p1[696320];
__device__ float  g_p2[696320];

static __device__ __forceinline__ uint32_t smem_u32(const void* p) {
    uint32_t a;
    asm("{ .reg .u64 t; cvta.to.shared.u64 t, %1; cvt.u32.u64 %0, t; }" : "=r"(a) : "l"(p));
    return a;
}
static __device__ __forceinline__ uint32_t pack_h2(float a, float b) {
    __half2 t = __floats2half2_rn(a, b);
    return *reinterpret_cast<uint32_t*>(&t);
}

#define LDSM4(r, addr)                                                          \
    asm volatile("ldmatrix.sync.aligned.m8n8.x4.shared.b16 {%0,%1,%2,%3}, [%4];" \
                 : "=r"((r)[0]), "=r"((r)[1]), "=r"((r)[2]), "=r"((r)[3])        \
                 : "r"(addr))

#define LDSM4T(r, addr)                                                              \
    asm volatile("ldmatrix.sync.aligned.m8n8.x4.trans.shared.b16 {%0,%1,%2,%3}, [%4];" \
                 : "=r"((r)[0]), "=r"((r)[1]), "=r"((r)[2]), "=r"((r)[3])            \
                 : "r"(addr))

#define MMA16816(d, a, b0, b1)                                                  \
    asm volatile("mma.sync.aligned.m16n8k16.row.col.f32.f16.f16.f32 "            \
                 "{%0,%1,%2,%3}, {%4,%5,%6,%7}, {%8,%9}, {%0,%1,%2,%3};"         \
                 : "+f"((d)[0]), "+f"((d)[1]), "+f"((d)[2]), "+f"((d)[3])        \
                 : "r"((a)[0]), "r"((a)[1]), "r"((a)[2]), "r"((a)[3]),           \
                   "r"(b0), "r"(b1))

// ---------------- kernel 1: pipelined HMMA GEMM ----------------
__global__ __launch_bounds__(256, 2)
void lg5_hmma(const float* __restrict__ x0, const float* __restrict__ x1,
              const float* __restrict__ x2, const float* __restrict__ x3,
              const float* __restrict__ x4,
              const float* __restrict__ f0, const float* __restrict__ f1,
              const float* __restrict__ f2, const float* __restrict__ f3,
              const float* __restrict__ f4,
              float* __restrict__ out) {
    extern __shared__ char smem[];
    __half* AH  = (__half*)smem;                  // 128 x PITCH (34816 B)
    __half* BH0 = (__half*)(smem + 34816);        // 32 x PITCHB (8704 B), k-major
    __half* BH1 = (__half*)(smem + 43520);        // 32 x PITCHB
    float*  T   = (float*)smem;                   // epilogue overlay (128 x FPITCH)

    __shared__ float sp1[2][128], sp2[2][128];

    // ---- level / tile decode (n-tiles of 128) ----
    const int bx = blockIdx.x;
    int L, t0;
    if (bx < 4096)      { L = 0; t0 = bx; }
    else if (bx < 5120) { L = 1; t0 = bx - 4096; }
    else if (bx < 5376) { L = 2; t0 = bx - 5120; }
    else if (bx < 5440) { L = 3; t0 = bx - 5376; }
    else                { L = 4; t0 = bx - 5440; }

    int N, nT;
    long long yoff;
    const float *X, *F;
    if (L == 0)      { N = 16384; nT = 128; yoff = 0LL;        X = x0; F = f0; }
    else if (L == 1) { N = 4096;  nT = 32;  yoff = 67108864LL; X = x1; F = f1; }
    else if (L == 2) { N = 1024;  nT = 8;   yoff = 83886080LL; X = x2; F = f2; }
    else if (L == 3) { N = 256;   nT = 2;   yoff = 88080384LL; X = x3; F = f3; }
    else             { N = 64;    nT = 1;   yoff = 89128960LL; X = x4; F = f4; }

    const int b    = t0 / nT;
    const int tile = t0 - b * nT;
    const int n0   = tile * 128;

    X += (size_t)b * 128 * N;
    F += (size_t)b * 128 * 128;

    const int tid = threadIdx.x;
    const int nvmax = N - n0;              // 128 normally; 64 for the L4 tail

    // B chunk mapping: lin = i*256+tid (i<4): k_local = lin>>5 (0..31), n = (lin&31)*4
    const int klc = tid >> 5;              // k_local base for i=0 contribution pattern
    (void)klc;

    float4 rb[4];
    const float4 z4 = make_float4(0.f, 0.f, 0.f, 0.f);

    // ---- prologue: issue chunk-0 LDGs ----
#pragma unroll
    for (int i = 0; i < 4; i++) {
        const int lin = i * 256 + tid;
        const int kl  = lin >> 5;
        const int n   = (lin & 31) * 4;
        rb[i] = (n < nvmax) ? *(const float4*)(X + (size_t)kl * N + n0 + n) : z4;
    }

    // ---- load F -> AH (overlaps chunk-0 LDG latency) ----
#pragma unroll
    for (int i = 0; i < 16; i++) {
        const int e   = (i * 256 + tid) * 4;
        const int row = e >> 7;
        const int k   = e & 127;
        const float4 f = *(const float4*)(F + e);
        uint2 hi2;
        hi2.x = pack_h2(f.x, f.y);
        hi2.y = pack_h2(f.z, f.w);
        *(uint2*)(AH + row * PITCH + k) = hi2;
    }

    // ---- store chunk 0 into BH0 ----
#pragma unroll
    for (int i = 0; i < 4; i++) {
        const int lin = i * 256 + tid;
        const int kl  = lin >> 5;
        const int n   = (lin & 31) * 4;
        uint2 h;
        h.x = pack_h2(rb[i].x, rb[i].y);
        h.y = pack_h2(rb[i].z, rb[i].w);
        *(uint2*)(BH0 + kl * PITCHB + n) = h;
    }
    __syncthreads();

    // ---- mainloop: 4 K-chunks of 32, double-buffered ----
    const int wid  = tid >> 5;
    const int lane = tid & 31;
    const int wm   = (wid >> 1) * 32;
    const int wn   = (wid & 1) * 64;

    float d[16][4];
#pragma unroll
    for (int i = 0; i < 16; i++)
#pragma unroll
        for (int j = 0; j < 4; j++) d[i][j] = 0.f;

    const int arow = lane & 15;
    const int acol = (lane >> 4) * 8;
    const int bkl  = lane & 15;            // k within k16 tile
    const int bnl  = (lane >> 4) * 8;      // n half within n16 tile

    const uint32_t aB0 = smem_u32(AH + (wm + arow) * PITCH + acol);
    const uint32_t aB1 = aB0 + 16 * PITCH * 2;
    const uint32_t bF0 = smem_u32(BH0 + bkl * PITCHB + wn + bnl);
    const uint32_t bF1 = smem_u32(BH1 + bkl * PITCHB + wn + bnl);

#pragma unroll
    for (int c = 0; c < 4; c++) {
        // prefetch next chunk (streaming LDG.128) while MMA runs below
        if (c < 3) {
            const int kb = (c + 1) * 32;
#pragma unroll
            for (int i = 0; i < 4; i++) {
                const int lin = i * 256 + tid;
                const int kl  = lin >> 5;
                const int n   = (lin & 31) * 4;
                rb[i] = (n < nvmax) ? *(const float4*)(X + (size_t)(kb + kl) * N + n0 + n) : z4;
            }
        }

        // MMA on current chunk (2 k-steps of 16)
        const uint32_t bBuf = (c & 1) ? bF1 : bF0;
#pragma unroll
        for (int ks = 0; ks < 2; ks++) {
            const uint32_t koA = (c * 2 + ks) * 32;
            const uint32_t koB = ks * 16 * PITCHB * 2;
            uint32_t bb[4][4];
#pragma unroll
            for (int t = 0; t < 4; t++)
                LDSM4T(bb[t], bBuf + koB + t * 32);

            uint32_t a0[4], a1[4];
            LDSM4(a0, aB0 + koA);
            LDSM4(a1, aB1 + koA);
#pragma unroll
            for (int t = 0; t < 4; t++) {
                MMA16816(d[2 * t + 0], a0, bb[t][0], bb[t][1]);
                MMA16816(d[2 * t + 1], a0, bb[t][2], bb[t][3]);
                MMA16816(d[2 * t + 8], a1, bb[t][0], bb[t][1]);
                MMA16816(d[2 * t + 9], a1, bb[t][2], bb[t][3]);
            }
        }

        // commit next chunk to the other buffer
        if (c < 3) {
            __half* dst = ((c + 1) & 1) ? BH1 : BH0;
#pragma unroll
            for (int i = 0; i < 4; i++) {
                const int lin = i * 256 + tid;
                const int kl  = lin >> 5;
                const int n   = (lin & 31) * 4;
                uint2 h;
                h.x = pack_h2(rb[i].x, rb[i].y);
                h.y = pack_h2(rb[i].z, rb[i].w);
                *(uint2*)(dst + kl * PITCHB + n) = h;
            }
            __syncthreads();
        }
    }

    // ---- partial stats from registers (levels 0-3), write-only ----
    if (L < 4) {
        float s1[4] = {0.f, 0.f, 0.f, 0.f}, s2[4] = {0.f, 0.f, 0.f, 0.f};
#pragma unroll
        for (int mi = 0; mi < 2; mi++)
#pragma unroll
            for (int nj = 0; nj < 8; nj++) {
                const float* dd = d[mi * 8 + nj];
                s1[mi * 2 + 0] += dd[0] + dd[1];
                s2[mi * 2 + 0] += dd[0] * dd[0] + dd[1] * dd[1];
                s1[mi * 2 + 1] += dd[2] + dd[3];
                s2[mi * 2 + 1] += dd[2] * dd[2] + dd[3] * dd[3];
            }
#pragma unroll
        for (int dlt = 1; dlt <= 2; dlt <<= 1)
#pragma unroll
            for (int i = 0; i < 4; i++) {
                s1[i] += __shfl_xor_sync(0xffffffffu, s1[i], dlt);
                s2[i] += __shfl_xor_sync(0xffffffffu, s2[i], dlt);
            }
        if ((lane & 3) == 0) {
#pragma unroll
            for (int i = 0; i < 4; i++) {
                const int row = wm + (i >> 1) * 16 + (i & 1) * 8 + (lane >> 2);
                sp1[wid & 1][row] = s1[i];
                sp2[wid & 1][row] = s2[i];
            }
        }
        __syncthreads();
        const long long poff = (L == 0) ? 0LL : (L == 1) ? 524288LL
                              : (L == 2) ? 655360LL : 688128LL;
        const size_t pidx = (size_t)poff + ((size_t)b * nT + tile) * 128 + tid;
        if (tid < 128) {
            g_p1[pidx] = sp1[0][tid] + sp1[1][tid];
            g_p2[pidx] = sp2[0][tid] + sp2[1][tid];
        }
    }
    __syncthreads();   // all warps done with AH/BH (and sp) before T overlay

    // ---- epilogue: d frags -> smem bounce -> coalesced store ----
#pragma unroll
    for (int mi = 0; mi < 2; mi++)
#pragma unroll
        for (int nj = 0; nj < 8; nj++) {
            const int row = wm + mi * 16 + (lane >> 2);
            const int col = wn + nj * 8 + 2 * (lane & 3);
            const float* dd = d[mi * 8 + nj];
            *(float2*)&T[row * FPITCH + col]       = make_float2(dd[0], dd[1]);
            *(float2*)&T[(row + 8) * FPITCH + col] = make_float2(dd[2], dd[3]);
        }
    __syncthreads();

    const int r0 = tid >> 5;
    const int c0 = (tid & 31) * 4;
    if (L < 4) {
        __half* Yh = g_yh + yoff + (size_t)b * 128 * N;
#pragma unroll
        for (int i = 0; i < 16; i++) {
            const int row = r0 + i * 8;
            const float4 v = *(const float4*)&T[row * FPITCH + c0];
            uint2 h;
            h.x = pack_h2(v.x, v.y);
            h.y = pack_h2(v.z, v.w);
            *(uint2*)&Yh[(size_t)row * N + n0 + c0] = h;
        }
    } else {
        float* Y = out + yoff + (size_t)b * 128 * N;
        const bool sv = (c0 < 64);   // N = 64, n0 = 0
#pragma unroll
        for (int i = 0; i < 16; i++) {
            const int row = r0 + i * 8;
            const float4 v = *(const float4*)&T[row * FPITCH + c0];
            if (sv) *(float4*)&Y[(size_t)row * N + c0] = v;
        }
    }
}

// ---------------- kernel 2: merged norm, grid (4096, 4) ----------------
template <int ITERS>
static __device__ __forceinline__
void norm_row(float* __restrict__ out, size_t yoff, int N, size_t poff, int nT, int bo) {
    const int b   = bo >> 7;
    const int o   = bo & 127;
    const int tid = threadIdx.x;

    const size_t pbase = poff + ((size_t)b * nT) * 128 + o;
    float s1 = 0.f, s2 = 0.f;
    for (int t = tid; t < nT; t += 256) {
        s1 += g_p1[pbase + (size_t)t * 128];
        s2 += g_p2[pbase + (size_t)t * 128];
    }
#pragma unroll
    for (int dl = 16; dl >= 1; dl >>= 1) {
        s1 += __shfl_xor_sync(0xffffffffu, s1, dl);
        s2 += __shfl_xor_sync(0xffffffffu, s2, dl);
    }
    __shared__ float a1[8], a2[8], st[2];
    const int w = tid >> 5, lane = tid & 31;
    if (lane == 0) { a1[w] = s1; a2[w] = s2; }
    __syncthreads();
    if (tid == 0) {
        float S1 = 0.f, S2 = 0.f;
#pragma unroll
        for (int i = 0; i < 8; i++) { S1 += a1[i]; S2 += a2[i]; }
        const float invN = 1.0f / (float)N;
        const float mean = S1 * invN;
        const float var  = S2 * invN - mean * mean;
        st[0] = mean;
        st[1] = rsqrtf(var + EPSN);
    }
    __syncthreads();
    const float mean = st[0], rstd = st[1];

    const __half* rh = g_yh + yoff + (size_t)bo * N;
    float*        rf = out  + yoff + (size_t)bo * N;
#pragma unroll
    for (int i = 0; i < ITERS; i++) {
        const int idx = (i * 256 + tid) * 8;
        if (idx < N) {
            const uint4 hv = *(const uint4*)(rh + idx);
            const uint32_t hw[4] = {hv.x, hv.y, hv.z, hv.w};
            float4 o0, o1;
            float* op[8] = {&o0.x, &o0.y, &o0.z, &o0.w, &o1.x, &o1.y, &o1.z, &o1.w};
#pragma unroll
            for (int j = 0; j < 4; j++) {
                const __half2 h2 = *reinterpret_cast<const __half2*>(&hw[j]);
                const float2 f2 = __half22float2(h2);
                *op[2 * j]     = (f2.x - mean) * rstd;
                *op[2 * j + 1] = (f2.y - mean) * rstd;
            }
            *(float4*)(rf + idx)     = o0;
            *(float4*)(rf + idx + 4) = o1;
        }
    }
}

__global__ __launch_bounds__(256)
void lg5_norm_all(float* __restrict__ out) {
    const int bo = blockIdx.x;
    if (blockIdx.y == 0)      norm_row<8>(out, 0,           16384, 0,      128, bo);
    else if (blockIdx.y == 1) norm_row<2>(out, 67108864ULL, 4096,  524288, 32,  bo);
    else if (blockIdx.y == 2) norm_row<1>(out, 83886080ULL, 1024,  655360, 8,   bo);
    else                      norm_row<1>(out, 88080384ULL, 256,   688128, 2,   bo);
}

// ---------------- launch ----------------
extern "C" void kernel_launch(void* const* d_in, const int* in_sizes, int n_in,
                              void* d_out, int out_size) {
    const float* xs[5] = {0, 0, 0, 0, 0};
    const float* fs[5] = {0, 0, 0, 0, 0};
    int fc = 0;
    for (int i = 0; i < n_in; i++) {
        const float* p = (const float*)d_in[i];
        switch (in_sizes[i]) {
            case 67108864: xs[0] = p; break;
            case 16777216: xs[1] = p; break;
            case 4194304:  xs[2] = p; break;
            case 1048576:  xs[3] = p; break;
            case 262144:   xs[4] = p; break;
            case 524288:   if (fc < 5) fs[fc++] = p; break;
        }
    }
    float* out = (float*)d_out;

    const int smem_bytes = 69632;  // max(AH + 2 B-chunks = 52224, epilogue T = 67584) padded
    cudaFuncSetAttribute(lg5_hmma, cudaFuncAttributeMaxDynamicSharedMemorySize, smem_bytes);
    lg5_hmma<<<5472, 256, smem_bytes>>>(xs[0], xs[1], xs[2], xs[3], xs[4],
                                        fs[0], fs[1], fs[2], fs[3], fs[4], out);

    lg5_norm_all<<<dim3(4096, 4), 256>>>(out);
}